// round 15
// baseline (speedup 1.0000x reference)
#include <cuda_runtime.h>
#include <cuda_fp16.h>

// NNUE forward, fused. v8:
//  - prologue: W_ft fp32->fp16 (flat, 4-way ILP, streaming) + W1 transpose fp16
//  - main: one CTA per batch row; 8 CTAs/SM; gather accumulates in fp16
//    (HFMA2 x4 per LDG.128), flushed to fp32 every 8 features (4 chunks);
//    (offset, half2 value) fused into one LDS.64; stage 2+3 float4-vectorized.
//
// Inputs (metadata order):
//  0 us(B) 1 them(B) 2 white_indices(B*32 i32) 3 white_values(B*32)
//  4 black_indices 5 black_values 6 layer_stack_indices(B i32)
//  7 W_ft(22528*1024) 8 b_ft(1024) 9 W1(1024*144) 10 b1(144)
// 11 W2(30*288) 12 b2(288) 13 W3(32*9) 14 b3(9)

#define KIDX   32
#define L1DIM  1024
#define L2DIM  15
#define L3DIM  32
#define NBUCK  9
#define NF     22528
#define W1COLS (NBUCK * (L2DIM + 1))   // 144
#define W2COLS (NBUCK * L3DIM)         // 288
#define FSC    (127.0f / 128.0f)

#define N4      ((size_t)NF * L1DIM / 4)       // 5,767,168 Half4 elements
#define CHUNK   (N4 / 4)                        // 1,441,792
#define CONV_BLOCKS ((int)(CHUNK / 256))        // 5632
#define W1N     (NBUCK * 16 * L1DIM)            // 147,456
#define W1_BLOCKS ((W1N + 255) / 256)           // 576

struct __align__(8) Half4 { __half2 a, b; };
struct __align__(8) OffVal { unsigned off; __half2 vh; };

__device__ Half4 g_Wft16[N4];                   // 46 MB fp16 copy of W_ft
__device__ Half4 g_W1t16[W1N / 4];              // 288 KB fp16 [bucket][j][e]

static __device__ __forceinline__ float clamp01(float x) {
    return fminf(fmaxf(x, 0.0f), 1.0f);
}

static __device__ __forceinline__ Half4 cvt4(float4 v) {
    Half4 h;
    h.a = __floats2half2_rn(v.x, v.y);
    h.b = __floats2half2_rn(v.z, v.w);
    return h;
}

// ---------------- prologue: convert W_ft + transpose W1 ----------------
__global__ __launch_bounds__(256)
void prologue_kernel(const float* __restrict__ W_ft,
                     const float* __restrict__ W1) {
    if (blockIdx.x < CONV_BLOCKS) {
        const size_t g = (size_t)blockIdx.x * 256 + threadIdx.x;
        const float4* src = reinterpret_cast<const float4*>(W_ft);
        const float4 v0 = __ldcs(&src[g]);
        const float4 v1 = __ldcs(&src[g + CHUNK]);
        const float4 v2 = __ldcs(&src[g + 2 * CHUNK]);
        const float4 v3 = __ldcs(&src[g + 3 * CHUNK]);
        g_Wft16[g]             = cvt4(v0);
        g_Wft16[g + CHUNK]     = cvt4(v1);
        g_Wft16[g + 2 * CHUNK] = cvt4(v2);
        g_Wft16[g + 3 * CHUNK] = cvt4(v3);
    } else {
        const int i = (blockIdx.x - CONV_BLOCKS) * 256 + threadIdx.x;
        if (i < W1N) {
            const int e   = i & (L1DIM - 1);
            const int j   = (i >> 10) & 15;
            const int bkt = i >> 14;
            reinterpret_cast<__half*>(g_W1t16)[i] =
                __float2half_rn(W1[(size_t)e * W1COLS + bkt * 16 + j]);
        }
    }
}

// ---------------- main fused kernel ----------------
__global__ __launch_bounds__(256, 8)
void nnue_fused_kernel(
    const float* __restrict__ us,   const float* __restrict__ them,
    const int*   __restrict__ widx, const float* __restrict__ wval,
    const int*   __restrict__ bidx, const float* __restrict__ bval,
    const int*   __restrict__ lsi,
    const float* __restrict__ b_ft,
    const float* __restrict__ b1,
    const float* __restrict__ W2,   const float* __restrict__ b2,
    const float* __restrict__ W3,   const float* __restrict__ b3,
    float* __restrict__ out)
{
    const int b = blockIdx.x;
    const int t = threadIdx.x;
    const int warp = t >> 5;
    const int lane = t & 31;

    __shared__ OffVal s_ov[2 * KIDX];      // fused (byte offset, half2 value)
    __shared__ float  s_a[L1DIM];          // raw wp
    __shared__ float  s_b[L1DIM];          // raw bp
    __shared__ float  s_l0p[L1DIM];        // pairwise-product activation
    __shared__ float  s_l1[16];            // l1c bucket slice

    // ---- stage 0: fused (offset, half2 value) into SMEM ----
    if (t < KIDX) {
        s_ov[t].off = (unsigned)widx[b * KIDX + t] * (L1DIM * 2u);
        s_ov[t].vh  = __float2half2_rn(wval[b * KIDX + t]);
    } else if (t < 2 * KIDX) {
        s_ov[t].off = (unsigned)bidx[b * KIDX + (t - KIDX)] * (L1DIM * 2u);
        s_ov[t].vh  = __float2half2_rn(bval[b * KIDX + (t - KIDX)]);
    }
    __syncthreads();

    // ---- stage 1: gather/accumulate; threads 0-127: wp, 128-255: bp ----
    // each thread owns 8 columns; fp16 accumulation in chunks of 8 features,
    // flushed into fp32 accumulators (4 flushes total).
    const int tl    = t & 127;
    const int kbase = (t < 128) ? 0 : KIDX;

    const float4* bft4 = reinterpret_cast<const float4*>(b_ft);
    float4 acc0 = bft4[2 * tl];
    float4 acc1 = bft4[2 * tl + 1];

    const char* wbase = reinterpret_cast<const char*>(g_Wft16);
    const unsigned lanebyte = (unsigned)tl * 16u;

    #pragma unroll
    for (int c8 = 0; c8 < 4; c8++) {
        __half2 h0 = __float2half2_rn(0.0f);
        __half2 h1 = h0, h2 = h0, h3 = h0;
        #pragma unroll
        for (int kk = 0; kk < 8; kk++) {
            const OffVal ov = s_ov[kbase + c8 * 8 + kk];
            const uint4 r = *reinterpret_cast<const uint4*>(
                wbase + ov.off + lanebyte);
            h0 = __hfma2(*reinterpret_cast<const __half2*>(&r.x), ov.vh, h0);
            h1 = __hfma2(*reinterpret_cast<const __half2*>(&r.y), ov.vh, h1);
            h2 = __hfma2(*reinterpret_cast<const __half2*>(&r.z), ov.vh, h2);
            h3 = __hfma2(*reinterpret_cast<const __half2*>(&r.w), ov.vh, h3);
        }
        const float2 f0 = __half22float2(h0);
        const float2 f1 = __half22float2(h1);
        const float2 f2 = __half22float2(h2);
        const float2 f3 = __half22float2(h3);
        acc0.x += f0.x; acc0.y += f0.y; acc0.z += f1.x; acc0.w += f1.y;
        acc1.x += f2.x; acc1.y += f2.y; acc1.z += f3.x; acc1.w += f3.y;
    }

    // stage raw wp into s_a (white threads), bp into s_b (black threads)
    {
        float4* dst = (t < 128) ? reinterpret_cast<float4*>(s_a)
                                : reinterpret_cast<float4*>(s_b);
        dst[2 * tl]     = acc0;
        dst[2 * tl + 1] = acc1;
    }
    __syncthreads();

    // ---- stage 2+3 merged, float4-vectorized ----
    // thread t<128: A-outputs l0p[4t..4t+3]; t>=128: B-outputs l0p[512+...]
    const float u  = us[b];
    const float th = them[b];
    {
        const float4* a4 = reinterpret_cast<const float4*>(s_a);
        const float4* b4 = reinterpret_cast<const float4*>(s_b);
        float4* o4 = reinterpret_cast<float4*>(s_l0p);
        const bool white = (t < 128);
        float4 x0 = a4[tl], y0 = b4[tl];
        float4 x5 = a4[tl + 128], y5 = b4[tl + 128];
        if (!white) {  // swap roles for the B (flipped-perspective) half
            float4 tmp = x0; x0 = y0; y0 = tmp;
            tmp = x5; x5 = y5; y5 = tmp;
        }
        float4 A0, A5, P;
        A0.x = clamp01(u * x0.x + th * y0.x);
        A0.y = clamp01(u * x0.y + th * y0.y);
        A0.z = clamp01(u * x0.z + th * y0.z);
        A0.w = clamp01(u * x0.w + th * y0.w);
        A5.x = clamp01(u * x5.x + th * y5.x);
        A5.y = clamp01(u * x5.y + th * y5.y);
        A5.z = clamp01(u * x5.z + th * y5.z);
        A5.w = clamp01(u * x5.w + th * y5.w);
        P.x = A0.x * A5.x * FSC;
        P.y = A0.y * A5.y * FSC;
        P.z = A0.z * A5.z * FSC;
        P.w = A0.w * A5.w * FSC;
        o4[(white ? 0 : 128) + tl] = P;
    }
    __syncthreads();

    // ---- stage 4: L1 — warp w computes outputs {2w, 2w+1} over 1024 elems ----
    const int bucket = lsi[b];
    {
        const Half4* wrow0 = g_W1t16
            + ((size_t)bucket * 16 + 2 * warp) * (L1DIM / 4);
        const Half4* wrow1 = wrow0 + (L1DIM / 4);
        const float4* x4 = reinterpret_cast<const float4*>(s_l0p);

        float v0 = 0.0f, v1 = 0.0f;
        #pragma unroll
        for (int i = 0; i < 8; i++) {
            const int e4 = i * 32 + lane;
            const float4 x  = x4[e4];
            const Half4  w0 = wrow0[e4];
            const Half4  w1 = wrow1[e4];
            const float2 l0 = __half22float2(w0.a);
            const float2 h0 = __half22float2(w0.b);
            const float2 l1 = __half22float2(w1.a);
            const float2 h1 = __half22float2(w1.b);
            v0 = fmaf(x.x, l0.x, v0); v0 = fmaf(x.y, l0.y, v0);
            v0 = fmaf(x.z, h0.x, v0); v0 = fmaf(x.w, h0.y, v0);
            v1 = fmaf(x.x, l1.x, v1); v1 = fmaf(x.y, l1.y, v1);
            v1 = fmaf(x.z, h1.x, v1); v1 = fmaf(x.w, h1.y, v1);
        }
        #pragma unroll
        for (int o = 16; o > 0; o >>= 1) {
            v0 += __shfl_xor_sync(0xffffffffu, v0, o);
            v1 += __shfl_xor_sync(0xffffffffu, v1, o);
        }
        if (lane == 0) {
            s_l1[2 * warp]     = v0 + b1[bucket * 16 + 2 * warp];
            s_l1[2 * warp + 1] = v1 + b1[bucket * 16 + 2 * warp + 1];
        }
    }
    __syncthreads();

    // ---- stage 5: L2 + L3 tail on warp 0 ----
    if (t < 32) {
        const float l1f = s_l1[15];          // pass-through term, NOT clipped
        float acc = b2[bucket * L3DIM + t];
        #pragma unroll
        for (int i = 0; i < L2DIM; i++) {
            const float x  = clamp01(s_l1[i]);
            const float wa = W2[(size_t)i * W2COLS + bucket * L3DIM + t];
            const float wb = W2[(size_t)(i + L2DIM) * W2COLS + bucket * L3DIM + t];
            acc = fmaf(x * x * FSC, wa, acc);
            acc = fmaf(x * FSC,     wb, acc);
        }
        const float l2x = clamp01(acc);
        float contrib = l2x * W3[t * NBUCK + bucket];
        #pragma unroll
        for (int o = 16; o > 0; o >>= 1)
            contrib += __shfl_xor_sync(0xffffffffu, contrib, o);
        if (t == 0) out[b] = contrib + b3[bucket] + l1f;
    }
}

extern "C" void kernel_launch(void* const* d_in, const int* in_sizes, int n_in,
                              void* d_out, int out_size) {
    const float* us   = (const float*)d_in[0];
    const float* them = (const float*)d_in[1];
    const int*   widx = (const int*)  d_in[2];
    const float* wval = (const float*)d_in[3];
    const int*   bidx = (const int*)  d_in[4];
    const float* bval = (const float*)d_in[5];
    const int*   lsi  = (const int*)  d_in[6];
    const float* W_ft = (const float*)d_in[7];
    const float* b_ft = (const float*)d_in[8];
    const float* W1   = (const float*)d_in[9];
    const float* b1   = (const float*)d_in[10];
    const float* W2   = (const float*)d_in[11];
    const float* b2   = (const float*)d_in[12];
    const float* W3   = (const float*)d_in[13];
    const float* b3   = (const float*)d_in[14];
    float* out = (float*)d_out;

    const int B = in_sizes[0];

    prologue_kernel<<<CONV_BLOCKS + W1_BLOCKS, 256>>>(W_ft, W1);

    nnue_fused_kernel<<<B, 256>>>(us, them, widx, wval, bidx, bval, lsi,
                                  b_ft, b1, W2, b2, W3, b3, out);
}

// round 16
// speedup vs baseline: 1.0005x; 1.0005x over previous
#include <cuda_runtime.h>
#include <cuda_fp16.h>

// NNUE forward, fused. v9:
//  - prologue: W_ft fp32->fp16 with 16-byte (uint4) stores, 2x ILP, streaming
//    loads + W1 transpose fp16 in trailing blocks
//  - main: v7 gather (fp32 FFMA, LDG.128, wp/bp thread split, 8 CTAs/SM)
//    + fused (offset,value) LDS.64 + float4-vectorized stage 2+3
//
// Inputs (metadata order):
//  0 us(B) 1 them(B) 2 white_indices(B*32 i32) 3 white_values(B*32)
//  4 black_indices 5 black_values 6 layer_stack_indices(B i32)
//  7 W_ft(22528*1024) 8 b_ft(1024) 9 W1(1024*144) 10 b1(144)
// 11 W2(30*288) 12 b2(288) 13 W3(32*9) 14 b3(9)

#define KIDX   32
#define L1DIM  1024
#define L2DIM  15
#define L3DIM  32
#define NBUCK  9
#define NF     22528
#define W1COLS (NBUCK * (L2DIM + 1))   // 144
#define W2COLS (NBUCK * L3DIM)         // 288
#define FSC    (127.0f / 128.0f)

#define N4      ((size_t)NF * L1DIM / 4)       // 5,767,168 Half4 elements
#define N8      (N4 / 2)                        // 2,883,584 uint4 outputs
#define HALF8   (N8 / 2)                        // 1,441,792
#define CONV_BLOCKS ((int)(HALF8 / 256))        // 5632
#define W1N     (NBUCK * 16 * L1DIM)            // 147,456
#define W1_BLOCKS ((W1N + 255) / 256)           // 576

struct __align__(8) Half4 { __half2 a, b; };
struct __align__(8) OffVal { unsigned off; float v; };

__device__ Half4 g_Wft16[N4];                   // 46 MB fp16 copy of W_ft
__device__ Half4 g_W1t16[W1N / 4];              // 288 KB fp16 [bucket][j][e]

static __device__ __forceinline__ float clamp01(float x) {
    return fminf(fmaxf(x, 0.0f), 1.0f);
}

static __device__ __forceinline__ uint4 pack8(float4 a, float4 b) {
    uint4 o;
    __half2 h0 = __floats2half2_rn(a.x, a.y);
    __half2 h1 = __floats2half2_rn(a.z, a.w);
    __half2 h2 = __floats2half2_rn(b.x, b.y);
    __half2 h3 = __floats2half2_rn(b.z, b.w);
    o.x = *reinterpret_cast<unsigned*>(&h0);
    o.y = *reinterpret_cast<unsigned*>(&h1);
    o.z = *reinterpret_cast<unsigned*>(&h2);
    o.w = *reinterpret_cast<unsigned*>(&h3);
    return o;
}

// ---------------- prologue: convert W_ft (16B stores) + transpose W1 ----------------
__global__ __launch_bounds__(256)
void prologue_kernel(const float* __restrict__ W_ft,
                     const float* __restrict__ W1) {
    if (blockIdx.x < CONV_BLOCKS) {
        const size_t g = (size_t)blockIdx.x * 256 + threadIdx.x;
        const float4* src = reinterpret_cast<const float4*>(W_ft);
        uint4* dst = reinterpret_cast<uint4*>(g_Wft16);
        // two independent 32B-read -> 16B-store chains (MLP=4 loads)
        const float4 a0 = __ldcs(&src[2 * g]);
        const float4 a1 = __ldcs(&src[2 * g + 1]);
        const float4 b0 = __ldcs(&src[2 * (g + HALF8)]);
        const float4 b1 = __ldcs(&src[2 * (g + HALF8) + 1]);
        dst[g]         = pack8(a0, a1);
        dst[g + HALF8] = pack8(b0, b1);
    } else {
        const int i = (blockIdx.x - CONV_BLOCKS) * 256 + threadIdx.x;
        if (i < W1N) {
            const int e   = i & (L1DIM - 1);
            const int j   = (i >> 10) & 15;
            const int bkt = i >> 14;
            reinterpret_cast<__half*>(g_W1t16)[i] =
                __float2half_rn(W1[(size_t)e * W1COLS + bkt * 16 + j]);
        }
    }
}

// ---------------- main fused kernel ----------------
__global__ __launch_bounds__(256, 8)
void nnue_fused_kernel(
    const float* __restrict__ us,   const float* __restrict__ them,
    const int*   __restrict__ widx, const float* __restrict__ wval,
    const int*   __restrict__ bidx, const float* __restrict__ bval,
    const int*   __restrict__ lsi,
    const float* __restrict__ b_ft,
    const float* __restrict__ b1,
    const float* __restrict__ W2,   const float* __restrict__ b2,
    const float* __restrict__ W3,   const float* __restrict__ b3,
    float* __restrict__ out)
{
    const int b = blockIdx.x;
    const int t = threadIdx.x;
    const int warp = t >> 5;
    const int lane = t & 31;

    __shared__ OffVal s_ov[2 * KIDX];      // fused (byte offset, value)
    __shared__ float  s_a[L1DIM];          // raw wp
    __shared__ float  s_b[L1DIM];          // raw bp
    __shared__ float  s_l0p[L1DIM];        // pairwise-product activation
    __shared__ float  s_l1[16];            // l1c bucket slice

    // ---- stage 0: fused (offset, value) into SMEM ----
    if (t < KIDX) {
        s_ov[t].off = (unsigned)widx[b * KIDX + t] * (L1DIM * 2u);
        s_ov[t].v   = wval[b * KIDX + t];
    } else if (t < 2 * KIDX) {
        s_ov[t].off = (unsigned)bidx[b * KIDX + (t - KIDX)] * (L1DIM * 2u);
        s_ov[t].v   = bval[b * KIDX + (t - KIDX)];
    }
    __syncthreads();

    // ---- stage 1: gather/accumulate; threads 0-127: wp, 128-255: bp ----
    // each thread owns 8 columns: 8*tl .. 8*tl+7  (tl = t & 127)
    const int tl    = t & 127;
    const int kbase = (t < 128) ? 0 : KIDX;

    const float4* bft4 = reinterpret_cast<const float4*>(b_ft);
    float4 acc0 = bft4[2 * tl];
    float4 acc1 = bft4[2 * tl + 1];

    const char* wbase = reinterpret_cast<const char*>(g_Wft16);
    const unsigned lanebyte = (unsigned)tl * 16u;

    #pragma unroll 8
    for (int k = 0; k < KIDX; k++) {
        const OffVal ov = s_ov[kbase + k];
        const uint4 r = *reinterpret_cast<const uint4*>(
            wbase + ov.off + lanebyte);
        const float  v  = ov.v;
        const float2 p0 = __half22float2(*reinterpret_cast<const __half2*>(&r.x));
        const float2 p1 = __half22float2(*reinterpret_cast<const __half2*>(&r.y));
        const float2 p2 = __half22float2(*reinterpret_cast<const __half2*>(&r.z));
        const float2 p3 = __half22float2(*reinterpret_cast<const __half2*>(&r.w));
        acc0.x = fmaf(v, p0.x, acc0.x); acc0.y = fmaf(v, p0.y, acc0.y);
        acc0.z = fmaf(v, p1.x, acc0.z); acc0.w = fmaf(v, p1.y, acc0.w);
        acc1.x = fmaf(v, p2.x, acc1.x); acc1.y = fmaf(v, p2.y, acc1.y);
        acc1.z = fmaf(v, p3.x, acc1.z); acc1.w = fmaf(v, p3.y, acc1.w);
    }

    // stage raw wp into s_a (white threads), bp into s_b (black threads)
    {
        float4* dst = (t < 128) ? reinterpret_cast<float4*>(s_a)
                                : reinterpret_cast<float4*>(s_b);
        dst[2 * tl]     = acc0;
        dst[2 * tl + 1] = acc1;
    }
    __syncthreads();

    // ---- stage 2+3 merged, float4-vectorized ----
    // thread t<128: A-outputs l0p[4tl..4tl+3]; t>=128: B-outputs l0p[512+4tl..]
    const float u  = us[b];
    const float th = them[b];
    {
        const float4* a4 = reinterpret_cast<const float4*>(s_a);
        const float4* b4 = reinterpret_cast<const float4*>(s_b);
        float4* o4 = reinterpret_cast<float4*>(s_l0p);
        const bool white = (t < 128);
        float4 x0 = a4[tl], y0 = b4[tl];
        float4 x5 = a4[tl + 128], y5 = b4[tl + 128];
        if (!white) {  // swap roles for the flipped-perspective half
            float4 tmp = x0; x0 = y0; y0 = tmp;
            tmp = x5; x5 = y5; y5 = tmp;
        }
        float4 A0, A5, P;
        A0.x = clamp01(u * x0.x + th * y0.x);
        A0.y = clamp01(u * x0.y + th * y0.y);
        A0.z = clamp01(u * x0.z + th * y0.z);
        A0.w = clamp01(u * x0.w + th * y0.w);
        A5.x = clamp01(u * x5.x + th * y5.x);
        A5.y = clamp01(u * x5.y + th * y5.y);
        A5.z = clamp01(u * x5.z + th * y5.z);
        A5.w = clamp01(u * x5.w + th * y5.w);
        P.x = A0.x * A5.x * FSC;
        P.y = A0.y * A5.y * FSC;
        P.z = A0.z * A5.z * FSC;
        P.w = A0.w * A5.w * FSC;
        o4[(white ? 0 : 128) + tl] = P;
    }
    __syncthreads();

    // ---- stage 4: L1 — warp w computes outputs {2w, 2w+1} over 1024 elems ----
    const int bucket = lsi[b];
    {
        const Half4* wrow0 = g_W1t16
            + ((size_t)bucket * 16 + 2 * warp) * (L1DIM / 4);
        const Half4* wrow1 = wrow0 + (L1DIM / 4);
        const float4* x4 = reinterpret_cast<const float4*>(s_l0p);

        float v0 = 0.0f, v1 = 0.0f;
        #pragma unroll
        for (int i = 0; i < 8; i++) {
            const int e4 = i * 32 + lane;
            const float4 x  = x4[e4];
            const Half4  w0 = wrow0[e4];
            const Half4  w1 = wrow1[e4];
            const float2 l0 = __half22float2(w0.a);
            const float2 h0 = __half22float2(w0.b);
            const float2 l1 = __half22float2(w1.a);
            const float2 h1 = __half22float2(w1.b);
            v0 = fmaf(x.x, l0.x, v0); v0 = fmaf(x.y, l0.y, v0);
            v0 = fmaf(x.z, h0.x, v0); v0 = fmaf(x.w, h0.y, v0);
            v1 = fmaf(x.x, l1.x, v1); v1 = fmaf(x.y, l1.y, v1);
            v1 = fmaf(x.z, h1.x, v1); v1 = fmaf(x.w, h1.y, v1);
        }
        #pragma unroll
        for (int o = 16; o > 0; o >>= 1) {
            v0 += __shfl_xor_sync(0xffffffffu, v0, o);
            v1 += __shfl_xor_sync(0xffffffffu, v1, o);
        }
        if (lane == 0) {
            s_l1[2 * warp]     = v0 + b1[bucket * 16 + 2 * warp];
            s_l1[2 * warp + 1] = v1 + b1[bucket * 16 + 2 * warp + 1];
        }
    }
    __syncthreads();

    // ---- stage 5: L2 + L3 tail on warp 0 ----
    if (t < 32) {
        const float l1f = s_l1[15];          // pass-through term, NOT clipped
        float acc = b2[bucket * L3DIM + t];
        #pragma unroll
        for (int i = 0; i < L2DIM; i++) {
            const float x  = clamp01(s_l1[i]);
            const float wa = W2[(size_t)i * W2COLS + bucket * L3DIM + t];
            const float wb = W2[(size_t)(i + L2DIM) * W2COLS + bucket * L3DIM + t];
            acc = fmaf(x * x * FSC, wa, acc);
            acc = fmaf(x * FSC,     wb, acc);
        }
        const float l2x = clamp01(acc);
        float contrib = l2x * W3[t * NBUCK + bucket];
        #pragma unroll
        for (int o = 16; o > 0; o >>= 1)
            contrib += __shfl_xor_sync(0xffffffffu, contrib, o);
        if (t == 0) out[b] = contrib + b3[bucket] + l1f;
    }
}

extern "C" void kernel_launch(void* const* d_in, const int* in_sizes, int n_in,
                              void* d_out, int out_size) {
    const float* us   = (const float*)d_in[0];
    const float* them = (const float*)d_in[1];
    const int*   widx = (const int*)  d_in[2];
    const float* wval = (const float*)d_in[3];
    const int*   bidx = (const int*)  d_in[4];
    const float* bval = (const float*)d_in[5];
    const int*   lsi  = (const int*)  d_in[6];
    const float* W_ft = (const float*)d_in[7];
    const float* b_ft = (const float*)d_in[8];
    const float* W1   = (const float*)d_in[9];
    const float* b1   = (const float*)d_in[10];
    const float* W2   = (const float*)d_in[11];
    const float* b2   = (const float*)d_in[12];
    const float* W3   = (const float*)d_in[13];
    const float* b3   = (const float*)d_in[14];
    float* out = (float*)d_out;

    const int B = in_sizes[0];

    prologue_kernel<<<CONV_BLOCKS + W1_BLOCKS, 256>>>(W_ft, W1);

    nnue_fused_kernel<<<B, 256>>>(us, them, widx, wval, bidx, bval, lsi,
                                  b_ft, b1, W2, b2, W3, b3, out);
}

// round 17
// speedup vs baseline: 1.0331x; 1.0325x over previous
#include <cuda_runtime.h>
#include <cuda_fp16.h>

// NNUE forward, fused. v10 = consolidation:
//  - prologue from v9: W_ft fp32->fp16 with 16-byte (uint4) stores, 2x ILP,
//    streaming loads; W1 transpose fp16 in trailing blocks
//  - main from v7 (best measured 47.5us): fp32 FFMA gather, LDG.128 wp/bp
//    thread split, 8 CTAs/SM, scalar merged stage 2+3
//
// Inputs (metadata order):
//  0 us(B) 1 them(B) 2 white_indices(B*32 i32) 3 white_values(B*32)
//  4 black_indices 5 black_values 6 layer_stack_indices(B i32)
//  7 W_ft(22528*1024) 8 b_ft(1024) 9 W1(1024*144) 10 b1(144)
// 11 W2(30*288) 12 b2(288) 13 W3(32*9) 14 b3(9)

#define KIDX   32
#define L1DIM  1024
#define L2DIM  15
#define L3DIM  32
#define NBUCK  9
#define NF     22528
#define W1COLS (NBUCK * (L2DIM + 1))   // 144
#define W2COLS (NBUCK * L3DIM)         // 288
#define FSC    (127.0f / 128.0f)

#define N4      ((size_t)NF * L1DIM / 4)       // 5,767,168 Half4 elements
#define N8      (N4 / 2)                        // 2,883,584 uint4 outputs
#define HALF8   (N8 / 2)                        // 1,441,792
#define CONV_BLOCKS ((int)(HALF8 / 256))        // 5632
#define W1N     (NBUCK * 16 * L1DIM)            // 147,456
#define W1_BLOCKS ((W1N + 255) / 256)           // 576

struct __align__(8) Half4 { __half2 a, b; };

__device__ Half4 g_Wft16[N4];                   // 46 MB fp16 copy of W_ft
__device__ Half4 g_W1t16[W1N / 4];              // 288 KB fp16 [bucket][j][e]

static __device__ __forceinline__ float clamp01(float x) {
    return fminf(fmaxf(x, 0.0f), 1.0f);
}

static __device__ __forceinline__ uint4 pack8(float4 a, float4 b) {
    uint4 o;
    __half2 h0 = __floats2half2_rn(a.x, a.y);
    __half2 h1 = __floats2half2_rn(a.z, a.w);
    __half2 h2 = __floats2half2_rn(b.x, b.y);
    __half2 h3 = __floats2half2_rn(b.z, b.w);
    o.x = *reinterpret_cast<unsigned*>(&h0);
    o.y = *reinterpret_cast<unsigned*>(&h1);
    o.z = *reinterpret_cast<unsigned*>(&h2);
    o.w = *reinterpret_cast<unsigned*>(&h3);
    return o;
}

// ---------------- prologue: convert W_ft (16B stores) + transpose W1 ----------------
__global__ __launch_bounds__(256)
void prologue_kernel(const float* __restrict__ W_ft,
                     const float* __restrict__ W1) {
    if (blockIdx.x < CONV_BLOCKS) {
        const size_t g = (size_t)blockIdx.x * 256 + threadIdx.x;
        const float4* src = reinterpret_cast<const float4*>(W_ft);
        uint4* dst = reinterpret_cast<uint4*>(g_Wft16);
        // two independent 32B-read -> 16B-store chains (MLP=4 loads)
        const float4 a0 = __ldcs(&src[2 * g]);
        const float4 a1 = __ldcs(&src[2 * g + 1]);
        const float4 b0 = __ldcs(&src[2 * (g + HALF8)]);
        const float4 b1 = __ldcs(&src[2 * (g + HALF8) + 1]);
        dst[g]         = pack8(a0, a1);
        dst[g + HALF8] = pack8(b0, b1);
    } else {
        const int i = (blockIdx.x - CONV_BLOCKS) * 256 + threadIdx.x;
        if (i < W1N) {
            const int e   = i & (L1DIM - 1);
            const int j   = (i >> 10) & 15;
            const int bkt = i >> 14;
            reinterpret_cast<__half*>(g_W1t16)[i] =
                __float2half_rn(W1[(size_t)e * W1COLS + bkt * 16 + j]);
        }
    }
}

// ---------------- main fused kernel (v7, best measured) ----------------
__global__ __launch_bounds__(256, 8)
void nnue_fused_kernel(
    const float* __restrict__ us,   const float* __restrict__ them,
    const int*   __restrict__ widx, const float* __restrict__ wval,
    const int*   __restrict__ bidx, const float* __restrict__ bval,
    const int*   __restrict__ lsi,
    const float* __restrict__ b_ft,
    const float* __restrict__ b1,
    const float* __restrict__ W2,   const float* __restrict__ b2,
    const float* __restrict__ W3,   const float* __restrict__ b3,
    float* __restrict__ out)
{
    const int b = blockIdx.x;
    const int t = threadIdx.x;
    const int warp = t >> 5;
    const int lane = t & 31;

    __shared__ unsigned s_off[2 * KIDX];   // byte offsets into g_Wft16
    __shared__ float    s_val[2 * KIDX];
    __shared__ float    s_a[L1DIM];        // raw wp
    __shared__ float    s_b[L1DIM];        // raw bp
    __shared__ float    s_l0p[L1DIM];      // pairwise-product activation
    __shared__ float    s_l1[16];          // l1c bucket slice

    // ---- stage 0: indices (as byte offsets) / values into SMEM ----
    if (t < KIDX) {
        s_off[t] = (unsigned)widx[b * KIDX + t] * (L1DIM * 2u);
        s_val[t] = wval[b * KIDX + t];
    } else if (t < 2 * KIDX) {
        s_off[t] = (unsigned)bidx[b * KIDX + (t - KIDX)] * (L1DIM * 2u);
        s_val[t] = bval[b * KIDX + (t - KIDX)];
    }
    __syncthreads();

    // ---- stage 1: gather/accumulate; threads 0-127: wp, 128-255: bp ----
    // each thread owns 8 columns: 8*tl .. 8*tl+7  (tl = t & 127)
    const int tl    = t & 127;
    const int kbase = (t < 128) ? 0 : KIDX;

    const float4* bft4 = reinterpret_cast<const float4*>(b_ft);
    float4 acc0 = bft4[2 * tl];
    float4 acc1 = bft4[2 * tl + 1];

    const char* wbase = reinterpret_cast<const char*>(g_Wft16);
    const unsigned lanebyte = (unsigned)tl * 16u;

    #pragma unroll 8
    for (int k = 0; k < KIDX; k++) {
        const unsigned off = s_off[kbase + k];
        const float    v   = s_val[kbase + k];
        const uint4 r = *reinterpret_cast<const uint4*>(wbase + off + lanebyte);
        const float2 p0 = __half22float2(*reinterpret_cast<const __half2*>(&r.x));
        const float2 p1 = __half22float2(*reinterpret_cast<const __half2*>(&r.y));
        const float2 p2 = __half22float2(*reinterpret_cast<const __half2*>(&r.z));
        const float2 p3 = __half22float2(*reinterpret_cast<const __half2*>(&r.w));
        acc0.x = fmaf(v, p0.x, acc0.x); acc0.y = fmaf(v, p0.y, acc0.y);
        acc0.z = fmaf(v, p1.x, acc0.z); acc0.w = fmaf(v, p1.y, acc0.w);
        acc1.x = fmaf(v, p2.x, acc1.x); acc1.y = fmaf(v, p2.y, acc1.y);
        acc1.z = fmaf(v, p3.x, acc1.z); acc1.w = fmaf(v, p3.y, acc1.w);
    }

    // stage raw wp into s_a (white threads), bp into s_b (black threads)
    {
        float4* dst = (t < 128) ? reinterpret_cast<float4*>(s_a)
                                : reinterpret_cast<float4*>(s_b);
        dst[2 * tl]     = acc0;
        dst[2 * tl + 1] = acc1;
    }
    __syncthreads();

    // ---- stage 2+3 merged: perspective combine + clamp + pairwise products ----
    const float u  = us[b];
    const float th = them[b];
    #pragma unroll
    for (int cix = t; cix < 512; cix += 256) {
        const float wpc  = s_a[cix],       bpc  = s_b[cix];
        const float wpc5 = s_a[cix + 512], bpc5 = s_b[cix + 512];
        const float A0 = clamp01(u * wpc  + th * bpc);
        const float A5 = clamp01(u * wpc5 + th * bpc5);
        const float B0 = clamp01(u * bpc  + th * wpc);
        const float B5 = clamp01(u * bpc5 + th * wpc5);
        s_l0p[cix]       = A0 * A5 * FSC;
        s_l0p[cix + 512] = B0 * B5 * FSC;
    }
    __syncthreads();

    // ---- stage 4: L1 — warp w computes outputs {2w, 2w+1} over 1024 elems ----
    const int bucket = lsi[b];
    {
        const Half4* wrow0 = g_W1t16
            + ((size_t)bucket * 16 + 2 * warp) * (L1DIM / 4);
        const Half4* wrow1 = wrow0 + (L1DIM / 4);
        const float4* x4 = reinterpret_cast<const float4*>(s_l0p);

        float v0 = 0.0f, v1 = 0.0f;
        #pragma unroll
        for (int i = 0; i < 8; i++) {
            const int e4 = i * 32 + lane;
            const float4 x  = x4[e4];
            const Half4  w0 = wrow0[e4];
            const Half4  w1 = wrow1[e4];
            const float2 l0 = __half22float2(w0.a);
            const float2 h0 = __half22float2(w0.b);
            const float2 l1 = __half22float2(w1.a);
            const float2 h1 = __half22float2(w1.b);
            v0 = fmaf(x.x, l0.x, v0); v0 = fmaf(x.y, l0.y, v0);
            v0 = fmaf(x.z, h0.x, v0); v0 = fmaf(x.w, h0.y, v0);
            v1 = fmaf(x.x, l1.x, v1); v1 = fmaf(x.y, l1.y, v1);
            v1 = fmaf(x.z, h1.x, v1); v1 = fmaf(x.w, h1.y, v1);
        }
        #pragma unroll
        for (int o = 16; o > 0; o >>= 1) {
            v0 += __shfl_xor_sync(0xffffffffu, v0, o);
            v1 += __shfl_xor_sync(0xffffffffu, v1, o);
        }
        if (lane == 0) {
            s_l1[2 * warp]     = v0 + b1[bucket * 16 + 2 * warp];
            s_l1[2 * warp + 1] = v1 + b1[bucket * 16 + 2 * warp + 1];
        }
    }
    __syncthreads();

    // ---- stage 5: L2 + L3 tail on warp 0 ----
    if (t < 32) {
        const float l1f = s_l1[15];          // pass-through term, NOT clipped
        float acc = b2[bucket * L3DIM + t];
        #pragma unroll
        for (int i = 0; i < L2DIM; i++) {
            const float x  = clamp01(s_l1[i]);
            const float wa = W2[(size_t)i * W2COLS + bucket * L3DIM + t];
            const float wb = W2[(size_t)(i + L2DIM) * W2COLS + bucket * L3DIM + t];
            acc = fmaf(x * x * FSC, wa, acc);
            acc = fmaf(x * FSC,     wb, acc);
        }
        const float l2x = clamp01(acc);
        float contrib = l2x * W3[t * NBUCK + bucket];
        #pragma unroll
        for (int o = 16; o > 0; o >>= 1)
            contrib += __shfl_xor_sync(0xffffffffu, contrib, o);
        if (t == 0) out[b] = contrib + b3[bucket] + l1f;
    }
}

extern "C" void kernel_launch(void* const* d_in, const int* in_sizes, int n_in,
                              void* d_out, int out_size) {
    const float* us   = (const float*)d_in[0];
    const float* them = (const float*)d_in[1];
    const int*   widx = (const int*)  d_in[2];
    const float* wval = (const float*)d_in[3];
    const int*   bidx = (const int*)  d_in[4];
    const float* bval = (const float*)d_in[5];
    const int*   lsi  = (const int*)  d_in[6];
    const float* W_ft = (const float*)d_in[7];
    const float* b_ft = (const float*)d_in[8];
    const float* W1   = (const float*)d_in[9];
    const float* b1   = (const float*)d_in[10];
    const float* W2   = (const float*)d_in[11];
    const float* b2   = (const float*)d_in[12];
    const float* W3   = (const float*)d_in[13];
    const float* b3   = (const float*)d_in[14];
    float* out = (float*)d_out;

    const int B = in_sizes[0];

    prologue_kernel<<<CONV_BLOCKS + W1_BLOCKS, 256>>>(W_ft, W1);

    nnue_fused_kernel<<<B, 256>>>(us, them, widx, wval, bidx, bval, lsi,
                                  b_ft, b1, W2, b2, W3, b3, out);
}